// round 1
// baseline (speedup 1.0000x reference)
#include <cuda_runtime.h>

// ============================================================================
// Compile-time generation of a pruned median-selection network.
//
// 1) Batcher odd-even mergesort network for n=32 (classic power-of-2 form).
// 2) Restrict to slots 0..24: conceptual +inf pads in slots 25..31 only ever
//    move toward higher indices, so any CE touching slot >=25 is a no-op on
//    the 25 real values -> drop it. Result: a valid sort-25 network.
// 3) Backward-slice for outputs {12,13}: walking the CE list in reverse, keep
//    a CE iff either endpoint is needed, and then mark both endpoints needed.
//    Dropped CEs can only perturb slots that never feed outputs 12/13.
// ============================================================================

struct P8 { unsigned char a, b; };

struct Net {
    int n;
    P8  p[256];
};

constexpr void oem_merge(int lo, int n, int r, P8* out, int& cnt) {
    int m = r * 2;
    if (m < n) {
        oem_merge(lo,     n, m, out, cnt);   // even subsequence
        oem_merge(lo + r, n, m, out, cnt);   // odd subsequence
        for (int i = lo + r; i + r < lo + n; i += m)
            out[cnt++] = P8{(unsigned char)i, (unsigned char)(i + r)};
    } else {
        out[cnt++] = P8{(unsigned char)lo, (unsigned char)(lo + r)};
    }
}

constexpr void oem_sort(int lo, int n, P8* out, int& cnt) {
    if (n > 1) {
        int m = n / 2;
        oem_sort(lo,     m, out, cnt);
        oem_sort(lo + m, m, out, cnt);
        oem_merge(lo, n, 1, out, cnt);
    }
}

constexpr Net build_net() {
    P8 all[256] = {};
    int cnt = 0;
    oem_sort(0, 32, all, cnt);               // 191 CEs for n=32

    // Restrict to the 25 real slots.
    P8 filt[256] = {};
    int fc = 0;
    for (int i = 0; i < cnt; ++i)
        if (all[i].a < 25 && all[i].b < 25)
            filt[fc++] = all[i];

    // Backward slice for outputs {12, 13}.
    bool need[25] = {};
    need[12] = true;
    need[13] = true;
    bool keep[256] = {};
    for (int i = fc - 1; i >= 0; --i) {
        if (need[filt[i].a] || need[filt[i].b]) {
            keep[i] = true;
            need[filt[i].a] = true;
            need[filt[i].b] = true;
        }
    }

    Net net = {};
    for (int i = 0; i < fc; ++i)
        if (keep[i])
            net.p[net.n++] = filt[i];
    return net;
}

__device__ constexpr Net NET = build_net();

// ============================================================================
// Kernel: one thread per output pixel. Single uniform path for interior and
// boundary via the +/-inf padding trick:
//   p invalid entries, ceil(p/2) filled with -inf (first), floor(p/2) with
//   +inf. Then lo = s[12] always; hi = s[13] if p odd else s[12].
//   out = 0.5*(lo+hi).
// ============================================================================

#ifndef MF_C
#define MF_C 3
#define MF_H 1024
#define MF_W 1024
#endif

__global__ __launch_bounds__(256)
void median5x5_kernel(const float* __restrict__ img, float* __restrict__ out) {
    constexpr int H = MF_H, W = MF_W;
    int tid = blockIdx.x * blockDim.x + threadIdx.x;
    if (tid >= MF_C * H * W) return;

    int x = tid & (W - 1);
    int y = (tid >> 10) & (H - 1);
    const float* cimg = img + (size_t)(tid >> 20) * (size_t)(H * W);

    float v[25];
    int inv = 0;  // count of invalid entries seen so far (drives -inf/+inf alternation)

#pragma unroll
    for (int ky = 0; ky < 5; ++ky) {
        int yy = y + ky - 2;
        bool vy = (yy >= 0) && (yy <= H - 2);
        int  yc = min(max(yy, 0), H - 1);
        const float* row = cimg + (size_t)yc * W;
#pragma unroll
        for (int kx = 0; kx < 5; ++kx) {
            int xx = x + kx - 2;
            bool vx = (xx >= 0) && (xx <= W - 2);
            int  xc = min(max(xx, 0), W - 1);
            float val = __ldg(row + xc);
            if (!(vy && vx)) {
                // first invalid -> -inf, second -> +inf, alternating
                val = __int_as_float((inv & 1) ? 0x7f800000u : 0xff800000u);
                ++inv;
            }
            v[ky * 5 + kx] = val;
        }
    }

    // Pruned selection network (all indices constant after full unroll).
#pragma unroll
    for (int i = 0; i < NET.n; ++i) {
        const int a = NET.p[i].a;
        const int b = NET.p[i].b;
        float mn = fminf(v[a], v[b]);
        float mx = fmaxf(v[a], v[b]);
        v[a] = mn;
        v[b] = mx;
    }

    float s12 = v[12];
    float s13 = v[13];
    float hi  = (inv & 1) ? s13 : s12;
    out[tid] = 0.5f * (s12 + hi);
}

extern "C" void kernel_launch(void* const* d_in, const int* in_sizes, int n_in,
                              void* d_out, int out_size) {
    const float* img = (const float*)d_in[0];
    float* out = (float*)d_out;
    int total = MF_C * MF_H * MF_W;
    int threads = 256;
    int blocks = (total + threads - 1) / threads;
    median5x5_kernel<<<blocks, threads>>>(img, out);
}

// round 5
// speedup vs baseline: 1.9356x; 1.9356x over previous
#include <cuda_runtime.h>

// ============================================================================
// Compile-time sorting/merging network machinery.
//
//  - Batcher odd-even mergesort for power-of-2 n (oem_sort), restriction to a
//    slot prefix (pads are inert), backward slicing for selected outputs.
//  - Generalized (arbitrary-size) Batcher odd-even merge on index lists
//    (oem2), verified exhaustively at compile time via the 0-1 principle.
//    Used to merge 5 sorted columns and select rank 12 only (interior pixels).
//    Falls back to the proven restricted-sort route if verification fails.
// ============================================================================

struct P8 { unsigned char a, b; };

struct Net {
    int n;
    P8  p[256];
};

constexpr void oem_merge(int lo, int n, int r, P8* out, int& cnt) {
    int m = r * 2;
    if (m < n) {
        oem_merge(lo,     n, m, out, cnt);
        oem_merge(lo + r, n, m, out, cnt);
        for (int i = lo + r; i + r < lo + n; i += m)
            out[cnt++] = P8{(unsigned char)i, (unsigned char)(i + r)};
    } else {
        out[cnt++] = P8{(unsigned char)lo, (unsigned char)(lo + r)};
    }
}

constexpr void oem_sort(int lo, int n, P8* out, int& cnt) {
    if (n > 1) {
        int m = n / 2;
        oem_sort(lo,     m, out, cnt);
        oem_sort(lo + m, m, out, cnt);
        oem_merge(lo, n, 1, out, cnt);
    }
}

// ---- Boundary network: sort-25 (from restricted sort-32), sliced for {12,13}.
constexpr Net build_boundary_net() {
    P8 all[256] = {};
    int cnt = 0;
    oem_sort(0, 32, all, cnt);

    P8 filt[256] = {};
    int fc = 0;
    for (int i = 0; i < cnt; ++i)
        if (all[i].a < 25 && all[i].b < 25)
            filt[fc++] = all[i];

    bool need[25] = {};
    need[12] = true;
    need[13] = true;
    bool keep[256] = {};
    for (int i = fc - 1; i >= 0; --i) {
        if (need[filt[i].a] || need[filt[i].b]) {
            keep[i] = true;
            need[filt[i].a] = true;
            need[filt[i].b] = true;
        }
    }

    Net net = {};
    for (int i = 0; i < fc; ++i)
        if (keep[i])
            net.p[net.n++] = filt[i];
    return net;
}

__device__ constexpr Net BNET = build_boundary_net();

// ---- sort-5 network: Batcher sort-8 restricted to slots < 5 (9 CEs).
struct Net5 { int n; P8 p[24]; };

constexpr Net5 build_sort5() {
    P8 all[64] = {};
    int cnt = 0;
    oem_sort(0, 8, all, cnt);
    Net5 s = {};
    for (int i = 0; i < cnt; ++i)
        if (all[i].a < 5 && all[i].b < 5)
            s.p[s.n++] = all[i];
    return s;
}

constexpr bool verify_sort5(const Net5& s) {
    for (int m = 0; m < 32; ++m) {
        int v[5] = {};
        for (int k = 0; k < 5; ++k) v[k] = (m >> k) & 1;
        for (int i = 0; i < s.n; ++i) {
            int a = s.p[i].a, b = s.p[i].b;
            if (v[a] > v[b]) { int t = v[a]; v[a] = v[b]; v[b] = t; }
        }
        for (int k = 0; k + 1 < 5; ++k)
            if (v[k] > v[k + 1]) return false;
    }
    return true;
}

__device__ constexpr Net5 S5 = build_sort5();
static_assert(verify_sort5(build_sort5()), "sort5 network invalid");

// ---- Generalized odd-even merge on index lists (Knuth 5.2.2-style).
constexpr void oem2(const int* A, int m, const int* B, int n, int* Z,
                    P8* ce, int& cnt) {
    if (m == 0) { for (int i = 0; i < n; ++i) Z[i] = B[i]; return; }
    if (n == 0) { for (int i = 0; i < m; ++i) Z[i] = A[i]; return; }
    if (m == 1 && n == 1) {
        ce[cnt++] = P8{(unsigned char)A[0], (unsigned char)B[0]};
        Z[0] = A[0]; Z[1] = B[0];
        return;
    }
    int Ae[25] = {}, Ao[25] = {}, Be[25] = {}, Bo[25] = {};
    int nae = 0, nao = 0, nbe = 0, nbo = 0;
    for (int i = 0; i < m; ++i) { if (i & 1) Ao[nao++] = A[i]; else Ae[nae++] = A[i]; }
    for (int i = 0; i < n; ++i) { if (i & 1) Bo[nbo++] = B[i]; else Be[nbe++] = B[i]; }
    int E[25] = {}, O[25] = {};
    oem2(Ae, nae, Be, nbe, E, ce, cnt);
    oem2(Ao, nao, Bo, nbo, O, ce, cnt);
    int ne = nae + nbe, no = nao + nbo;
    Z[0] = E[0];
    int zi = 1;
    int i = 0;
    for (; i < no && i + 1 < ne; ++i) {
        ce[cnt++] = P8{(unsigned char)O[i], (unsigned char)E[i + 1]};
        Z[zi++] = O[i];
        Z[zi++] = E[i + 1];
    }
    for (; i < no; ++i) Z[zi++] = O[i];
    for (int j = i + 1; j < ne; ++j) Z[zi++] = E[j];
}

// Exhaustive 0-1 verification of one merge stage in isolation.
constexpr bool verify_merge(const P8* ce, int ibeg, int iend,
                            const int* A, int m, const int* B, int n,
                            const int* Z) {
    for (int i = 0; i <= m; ++i) {
        for (int j = 0; j <= n; ++j) {
            int v[25] = {};
            for (int k = 0; k < m; ++k) v[A[k]] = (k >= m - i) ? 1 : 0;
            for (int k = 0; k < n; ++k) v[B[k]] = (k >= n - j) ? 1 : 0;
            for (int t = ibeg; t < iend; ++t) {
                int a = ce[t].a, b = ce[t].b;
                if (v[a] > v[b]) { int tmp = v[a]; v[a] = v[b]; v[b] = tmp; }
            }
            for (int k = 0; k + 1 < m + n; ++k)
                if (v[Z[k]] > v[Z[k + 1]]) return false;
        }
    }
    return true;
}

// ---- Per-pixel interior network: merge 5 sorted columns, sliced for rank 12.
struct PixNet { int n; P8 p[256]; int outslot; int merged; };

constexpr PixNet build_pixnet() {
    P8 ce[256] = {};
    int cnt = 0;
    int s0[5] = {0, 1, 2, 3, 4};
    int s1[5] = {5, 6, 7, 8, 9};
    int s2[5] = {10, 11, 12, 13, 14};
    int s3[5] = {15, 16, 17, 18, 19};
    int s4[5] = {20, 21, 22, 23, 24};
    int m01[10] = {}, m23[10] = {}, m0123[20] = {}, mf[25] = {};

    int b0 = cnt; oem2(s0, 5, s1, 5, m01, ce, cnt);       int e0 = cnt;
    int b1 = cnt; oem2(s2, 5, s3, 5, m23, ce, cnt);       int e1 = cnt;
    int b2 = cnt; oem2(m01, 10, m23, 10, m0123, ce, cnt); int e2 = cnt;
    int b3 = cnt; oem2(m0123, 20, s4, 5, mf, ce, cnt);    int e3 = cnt;

    bool ok = verify_merge(ce, b0, e0, s0, 5, s1, 5, m01)
           && verify_merge(ce, b1, e1, s2, 5, s3, 5, m23)
           && verify_merge(ce, b2, e2, m01, 10, m23, 10, m0123)
           && verify_merge(ce, b3, e3, m0123, 20, s4, 5, mf);

    PixNet pn = {};
    if (ok) {
        pn.outslot = mf[12];
        pn.merged = 1;
        bool need[25] = {};
        need[pn.outslot] = true;
        bool keep[256] = {};
        for (int i = cnt - 1; i >= 0; --i) {
            if (need[ce[i].a] || need[ce[i].b]) {
                keep[i] = true;
                need[ce[i].a] = true;
                need[ce[i].b] = true;
            }
        }
        for (int i = 0; i < cnt; ++i)
            if (keep[i]) pn.p[pn.n++] = ce[i];
    } else {
        // Fallback: proven restricted sort-25, sliced for {12}.
        P8 all[256] = {};
        int scnt = 0;
        oem_sort(0, 32, all, scnt);
        P8 filt[256] = {};
        int fc = 0;
        for (int i = 0; i < scnt; ++i)
            if (all[i].a < 25 && all[i].b < 25)
                filt[fc++] = all[i];
        bool need[25] = {};
        need[12] = true;
        bool keep[256] = {};
        for (int i = fc - 1; i >= 0; --i) {
            if (need[filt[i].a] || need[filt[i].b]) {
                keep[i] = true;
                need[filt[i].a] = true;
                need[filt[i].b] = true;
            }
        }
        for (int i = 0; i < fc; ++i)
            if (keep[i]) pn.p[pn.n++] = filt[i];
        pn.outslot = 12;
        pn.merged = 0;
    }
    return pn;
}

__device__ constexpr PixNet PIX = build_pixnet();

// ============================================================================
// Kernels
// ============================================================================

#define MF_C 3
#define MF_H 1024
#define MF_W 1024

// ---- Interior: y,x in [2,1020]. No masks/clamps; exact median of 25.
// Each thread: 4 pixels along x, sharing 8 sorted columns.
// x-chunk t covers x0 = 2+4t .. x0+3; loads cols 4t..4t+7 (two aligned float4
// per row).
__global__ __launch_bounds__(128)
void median_interior(const float* __restrict__ img, float* __restrict__ out) {
    int t = blockIdx.x * blockDim.x + threadIdx.x;
    if (t >= 255) return;                      // 255 chunks cover x=2..1020
    int y = blockIdx.y + 2;                    // 2..1020
    int c = blockIdx.z;

    const float* base = img + ((size_t)c << 20) + (size_t)(y - 2) * MF_W + 4 * t;

    float col[8][5];
#pragma unroll
    for (int k = 0; k < 5; ++k) {
        float4 a = *reinterpret_cast<const float4*>(base + (size_t)k * MF_W);
        float4 b = *reinterpret_cast<const float4*>(base + (size_t)k * MF_W + 4);
        col[0][k] = a.x; col[1][k] = a.y; col[2][k] = a.z; col[3][k] = a.w;
        col[4][k] = b.x; col[5][k] = b.y; col[6][k] = b.z; col[7][k] = b.w;
    }

    // Sort the 8 columns; CE-index outer loop interleaves 8 independent
    // compare-exchange chains for ILP.
#pragma unroll
    for (int i = 0; i < S5.n; ++i) {
        const int a = S5.p[i].a, b = S5.p[i].b;
#pragma unroll
        for (int j = 0; j < 8; ++j) {
            float mn = fminf(col[j][a], col[j][b]);
            float mx = fmaxf(col[j][a], col[j][b]);
            col[j][a] = mn;
            col[j][b] = mx;
        }
    }

    int x0 = 2 + 4 * t;
    float* orow = out + ((size_t)c << 20) + (size_t)y * MF_W;
    bool full = (t < 254);                     // only the last chunk is partial

    float r[4];
#pragma unroll
    for (int p = 0; p < 4; ++p) {
        float w[25];
#pragma unroll
        for (int j = 0; j < 5; ++j)
#pragma unroll
            for (int k = 0; k < 5; ++k)
                w[j * 5 + k] = col[p + j][k];

#pragma unroll
        for (int i = 0; i < PIX.n; ++i) {
            const int a = PIX.p[i].a, b = PIX.p[i].b;
            float mn = fminf(w[a], w[b]);
            float mx = fmaxf(w[a], w[b]);
            w[a] = mn;
            w[b] = mx;
        }
        r[p] = w[PIX.outslot];
    }

    if (full) {
#pragma unroll
        for (int p = 0; p < 4; ++p) orow[x0 + p] = r[p];
    } else {
#pragma unroll
        for (int p = 0; p < 4; ++p)
            if (x0 + p <= MF_W - 4) orow[x0 + p] = r[p];
    }
}

// ---- Boundary: the 10215 pixels/channel with y<2, y>1020, x<2 or x>1020.
// General path with clamp + alternating -inf/+inf padding (proven in R1).
__global__ __launch_bounds__(256)
void median_boundary(const float* __restrict__ img, float* __restrict__ out) {
    constexpr int H = MF_H, W = MF_W;
    int b = blockIdx.x * blockDim.x + threadIdx.x;
    if (b >= 10215) return;
    int c = blockIdx.y;

    int y, x;
    if (b < 2048) {                     // rows 0..1
        y = b >> 10; x = b & 1023;
    } else if (b < 5120) {              // rows 1021..1023
        int r = b - 2048; y = 1021 + (r >> 10); x = r & 1023;
    } else {                            // rows 2..1020, cols {0,1,1021,1022,1023}
        int r = b - 5120;
        int q = r / 5;
        int s = r - q * 5;
        y = 2 + q;
        x = (s < 2) ? s : 1019 + s;
    }

    const float* cimg = img + ((size_t)c << 20);

    float v[25];
    int inv = 0;

#pragma unroll
    for (int ky = 0; ky < 5; ++ky) {
        int yy = y + ky - 2;
        bool vy = (yy >= 0) && (yy <= H - 2);
        int  yc = min(max(yy, 0), H - 1);
        const float* row = cimg + (size_t)yc * W;
#pragma unroll
        for (int kx = 0; kx < 5; ++kx) {
            int xx = x + kx - 2;
            bool vx = (xx >= 0) && (xx <= W - 2);
            int  xc = min(max(xx, 0), W - 1);
            float val = __ldg(row + xc);
            if (!(vy && vx)) {
                val = __int_as_float((inv & 1) ? 0x7f800000u : 0xff800000u);
                ++inv;
            }
            v[ky * 5 + kx] = val;
        }
    }

#pragma unroll
    for (int i = 0; i < BNET.n; ++i) {
        const int a = BNET.p[i].a, b2 = BNET.p[i].b;
        float mn = fminf(v[a], v[b2]);
        float mx = fmaxf(v[a], v[b2]);
        v[a] = mn;
        v[b2] = mx;
    }

    float s12 = v[12];
    float s13 = v[13];
    float hi  = (inv & 1) ? s13 : s12;
    out[((size_t)c << 20) + (size_t)y * W + x] = 0.5f * (s12 + hi);
}

extern "C" void kernel_launch(void* const* d_in, const int* in_sizes, int n_in,
                              void* d_out, int out_size) {
    const float* img = (const float*)d_in[0];
    float* out = (float*)d_out;

    dim3 gi(2, MF_H - 5, MF_C);            // 2*128 threads cover 255 chunks; 1019 rows
    median_interior<<<gi, 128>>>(img, out);

    dim3 gb((10215 + 255) / 256, MF_C, 1);
    median_boundary<<<gb, 256>>>(img, out);
}

// round 6
// speedup vs baseline: 2.1875x; 1.1301x over previous
#include <cuda_runtime.h>

// ============================================================================
// Compile-time sorting/merging network machinery.
//
//  - Batcher odd-even mergesort for power-of-2 n (oem_sort), restriction to a
//    slot prefix (pads are inert), backward slicing for selected outputs.
//  - Generalized (arbitrary-size) Batcher odd-even merge on index lists
//    (oem2), verified exhaustively at compile time via the 0-1 principle.
//  - NEW: op-level pruning. The backward slice records, per kept
//    compare-exchange, whether the downstream computation needs its min
//    output, its max output, or both. Single-sided CEs emit one fminf/fmaxf
//    instead of two. Need-propagation is unchanged (a single-op CE still
//    reads both wires), so correctness of the slice is preserved: a wire
//    left stale by a single-op CE is, by construction of the backward pass,
//    never read by any kept later CE or output.
// ============================================================================

struct P8 { unsigned char a, b; };
struct CE3 { unsigned char a, b, op; };   // op: 0=both, 1=min-only, 2=max-only

struct Net {
    int n;
    CE3 p[256];
};

constexpr void oem_merge(int lo, int n, int r, P8* out, int& cnt) {
    int m = r * 2;
    if (m < n) {
        oem_merge(lo,     n, m, out, cnt);
        oem_merge(lo + r, n, m, out, cnt);
        for (int i = lo + r; i + r < lo + n; i += m)
            out[cnt++] = P8{(unsigned char)i, (unsigned char)(i + r)};
    } else {
        out[cnt++] = P8{(unsigned char)lo, (unsigned char)(lo + r)};
    }
}

constexpr void oem_sort(int lo, int n, P8* out, int& cnt) {
    if (n > 1) {
        int m = n / 2;
        oem_sort(lo,     m, out, cnt);
        oem_sort(lo + m, m, out, cnt);
        oem_merge(lo, n, 1, out, cnt);
    }
}

// Backward slice with per-output need tracking; returns pruned op-annotated net.
constexpr Net slice_net(const P8* ce, int cnt, const bool* outputs_needed) {
    bool need[25] = {};
    for (int i = 0; i < 25; ++i) need[i] = outputs_needed[i];
    signed char op[256] = {};
    bool keep[256] = {};
    for (int i = cnt - 1; i >= 0; --i) {
        bool na = need[ce[i].a], nb = need[ce[i].b];
        if (!na && !nb) continue;
        keep[i] = true;
        op[i] = (na && nb) ? 0 : (na ? 1 : 2);
        need[ce[i].a] = true;
        need[ce[i].b] = true;
    }
    Net net = {};
    for (int i = 0; i < cnt; ++i)
        if (keep[i])
            net.p[net.n++] = CE3{ce[i].a, ce[i].b, (unsigned char)op[i]};
    return net;
}

// ---- Boundary network: sort-25 (from restricted sort-32), sliced for {12,13}.
constexpr Net build_boundary_net() {
    P8 all[256] = {};
    int cnt = 0;
    oem_sort(0, 32, all, cnt);

    P8 filt[256] = {};
    int fc = 0;
    for (int i = 0; i < cnt; ++i)
        if (all[i].a < 25 && all[i].b < 25)
            filt[fc++] = all[i];

    bool outs[25] = {};
    outs[12] = true;
    outs[13] = true;
    return slice_net(filt, fc, outs);
}

__device__ constexpr Net BNET = build_boundary_net();

// ---- sort-5 network: Batcher sort-8 restricted to slots < 5 (9 CEs, full).
struct Net5 { int n; P8 p[24]; };

constexpr Net5 build_sort5() {
    P8 all[64] = {};
    int cnt = 0;
    oem_sort(0, 8, all, cnt);
    Net5 s = {};
    for (int i = 0; i < cnt; ++i)
        if (all[i].a < 5 && all[i].b < 5)
            s.p[s.n++] = all[i];
    return s;
}

constexpr bool verify_sort5(const Net5& s) {
    for (int m = 0; m < 32; ++m) {
        int v[5] = {};
        for (int k = 0; k < 5; ++k) v[k] = (m >> k) & 1;
        for (int i = 0; i < s.n; ++i) {
            int a = s.p[i].a, b = s.p[i].b;
            if (v[a] > v[b]) { int t = v[a]; v[a] = v[b]; v[b] = t; }
        }
        for (int k = 0; k + 1 < 5; ++k)
            if (v[k] > v[k + 1]) return false;
    }
    return true;
}

__device__ constexpr Net5 S5 = build_sort5();
static_assert(verify_sort5(build_sort5()), "sort5 network invalid");

// ---- Generalized odd-even merge on index lists (Knuth 5.2.2-style).
constexpr void oem2(const int* A, int m, const int* B, int n, int* Z,
                    P8* ce, int& cnt) {
    if (m == 0) { for (int i = 0; i < n; ++i) Z[i] = B[i]; return; }
    if (n == 0) { for (int i = 0; i < m; ++i) Z[i] = A[i]; return; }
    if (m == 1 && n == 1) {
        ce[cnt++] = P8{(unsigned char)A[0], (unsigned char)B[0]};
        Z[0] = A[0]; Z[1] = B[0];
        return;
    }
    int Ae[25] = {}, Ao[25] = {}, Be[25] = {}, Bo[25] = {};
    int nae = 0, nao = 0, nbe = 0, nbo = 0;
    for (int i = 0; i < m; ++i) { if (i & 1) Ao[nao++] = A[i]; else Ae[nae++] = A[i]; }
    for (int i = 0; i < n; ++i) { if (i & 1) Bo[nbo++] = B[i]; else Be[nbe++] = B[i]; }
    int E[25] = {}, O[25] = {};
    oem2(Ae, nae, Be, nbe, E, ce, cnt);
    oem2(Ao, nao, Bo, nbo, O, ce, cnt);
    int ne = nae + nbe, no = nao + nbo;
    Z[0] = E[0];
    int zi = 1;
    int i = 0;
    for (; i < no && i + 1 < ne; ++i) {
        ce[cnt++] = P8{(unsigned char)O[i], (unsigned char)E[i + 1]};
        Z[zi++] = O[i];
        Z[zi++] = E[i + 1];
    }
    for (; i < no; ++i) Z[zi++] = O[i];
    for (int j = i + 1; j < ne; ++j) Z[zi++] = E[j];
}

// Exhaustive 0-1 verification of one merge stage in isolation.
constexpr bool verify_merge(const P8* ce, int ibeg, int iend,
                            const int* A, int m, const int* B, int n,
                            const int* Z) {
    for (int i = 0; i <= m; ++i) {
        for (int j = 0; j <= n; ++j) {
            int v[25] = {};
            for (int k = 0; k < m; ++k) v[A[k]] = (k >= m - i) ? 1 : 0;
            for (int k = 0; k < n; ++k) v[B[k]] = (k >= n - j) ? 1 : 0;
            for (int t = ibeg; t < iend; ++t) {
                int a = ce[t].a, b = ce[t].b;
                if (v[a] > v[b]) { int tmp = v[a]; v[a] = v[b]; v[b] = tmp; }
            }
            for (int k = 0; k + 1 < m + n; ++k)
                if (v[Z[k]] > v[Z[k + 1]]) return false;
        }
    }
    return true;
}

// ---- Per-pixel interior network: merge 5 sorted columns, sliced for rank 12.
struct PixNet { int n; CE3 p[256]; int outslot; int merged; };

constexpr PixNet build_pixnet() {
    P8 ce[256] = {};
    int cnt = 0;
    int s0[5] = {0, 1, 2, 3, 4};
    int s1[5] = {5, 6, 7, 8, 9};
    int s2[5] = {10, 11, 12, 13, 14};
    int s3[5] = {15, 16, 17, 18, 19};
    int s4[5] = {20, 21, 22, 23, 24};
    int m01[10] = {}, m23[10] = {}, m0123[20] = {}, mf[25] = {};

    int b0 = cnt; oem2(s0, 5, s1, 5, m01, ce, cnt);       int e0 = cnt;
    int b1 = cnt; oem2(s2, 5, s3, 5, m23, ce, cnt);       int e1 = cnt;
    int b2 = cnt; oem2(m01, 10, m23, 10, m0123, ce, cnt); int e2 = cnt;
    int b3 = cnt; oem2(m0123, 20, s4, 5, mf, ce, cnt);    int e3 = cnt;

    bool ok = verify_merge(ce, b0, e0, s0, 5, s1, 5, m01)
           && verify_merge(ce, b1, e1, s2, 5, s3, 5, m23)
           && verify_merge(ce, b2, e2, m01, 10, m23, 10, m0123)
           && verify_merge(ce, b3, e3, m0123, 20, s4, 5, mf);

    PixNet pn = {};
    if (ok) {
        bool outs[25] = {};
        outs[mf[12]] = true;
        Net s = slice_net(ce, cnt, outs);
        pn.n = s.n;
        for (int i = 0; i < s.n; ++i) pn.p[i] = s.p[i];
        pn.outslot = mf[12];
        pn.merged = 1;
    } else {
        // Fallback: proven restricted sort-25, sliced for {12}.
        P8 all[256] = {};
        int scnt = 0;
        oem_sort(0, 32, all, scnt);
        P8 filt[256] = {};
        int fc = 0;
        for (int i = 0; i < scnt; ++i)
            if (all[i].a < 25 && all[i].b < 25)
                filt[fc++] = all[i];
        bool outs[25] = {};
        outs[12] = true;
        Net s = slice_net(filt, fc, outs);
        pn.n = s.n;
        for (int i = 0; i < s.n; ++i) pn.p[i] = s.p[i];
        pn.outslot = 12;
        pn.merged = 0;
    }
    return pn;
}

__device__ constexpr PixNet PIX = build_pixnet();

// ============================================================================
// Fused kernel
// ============================================================================

#define MF_C 3
#define MF_H 1024
#define MF_W 1024

// Boundary region: 10215 px/channel (rows 0-1, rows 1021-1023, plus cols
// {0,1,1021,1022,1023} of rows 2..1020) -> 30645 px total -> 240 blocks of 128.
// Interior: x-chunks t in [0,255) x rows y in [2,1021) x 3 channels, 2 blocks
// of 128 per (row, channel) -> 6114 blocks.
#define NB_BOUND 240
#define NB_INNER 6114

__global__ __launch_bounds__(128)
void median_fused(const float* __restrict__ img, float* __restrict__ out) {
    constexpr int H = MF_H, W = MF_W;
    int blk = blockIdx.x;

    if (blk >= NB_BOUND) {
        // -------------------- Interior path --------------------
        int ib = blk - NB_BOUND;                 // 0 .. 6113
        int bx = ib & 1;                         // 2 blocks per row-chunk strip
        int rem = ib >> 1;                       // 0 .. 3056
        int yrow = rem % 1019;                   // 0 .. 1018
        int c = rem / 1019;                      // 0 .. 2
        int t = bx * 128 + threadIdx.x;
        if (t >= 255) return;
        int y = yrow + 2;

        const float* base = img + ((size_t)c << 20) + (size_t)(y - 2) * W + 4 * t;

        float col[8][5];
#pragma unroll
        for (int k = 0; k < 5; ++k) {
            float4 a = *reinterpret_cast<const float4*>(base + (size_t)k * W);
            float4 b = *reinterpret_cast<const float4*>(base + (size_t)k * W + 4);
            col[0][k] = a.x; col[1][k] = a.y; col[2][k] = a.z; col[3][k] = a.w;
            col[4][k] = b.x; col[5][k] = b.y; col[6][k] = b.z; col[7][k] = b.w;
        }

        // Sort the 8 columns; CE-index outer loop interleaves 8 chains for ILP.
#pragma unroll
        for (int i = 0; i < S5.n; ++i) {
            const int a = S5.p[i].a, b = S5.p[i].b;
#pragma unroll
            for (int j = 0; j < 8; ++j) {
                float mn = fminf(col[j][a], col[j][b]);
                float mx = fmaxf(col[j][a], col[j][b]);
                col[j][a] = mn;
                col[j][b] = mx;
            }
        }

        int x0 = 2 + 4 * t;
        float* orow = out + ((size_t)c << 20) + (size_t)y * W;
        bool full = (t < 254);

        float r[4];
#pragma unroll
        for (int p = 0; p < 4; ++p) {
            float w[25];
#pragma unroll
            for (int j = 0; j < 5; ++j)
#pragma unroll
                for (int k = 0; k < 5; ++k)
                    w[j * 5 + k] = col[p + j][k];

#pragma unroll
            for (int i = 0; i < PIX.n; ++i) {
                const int a = PIX.p[i].a, b = PIX.p[i].b;
                const int op = PIX.p[i].op;
                if (op == 0) {
                    float mn = fminf(w[a], w[b]);
                    float mx = fmaxf(w[a], w[b]);
                    w[a] = mn;
                    w[b] = mx;
                } else if (op == 1) {
                    w[a] = fminf(w[a], w[b]);
                } else {
                    w[b] = fmaxf(w[a], w[b]);
                }
            }
            r[p] = w[PIX.outslot];
        }

        if (full) {
#pragma unroll
            for (int p = 0; p < 4; ++p) orow[x0 + p] = r[p];
        } else {
#pragma unroll
            for (int p = 0; p < 4; ++p)
                if (x0 + p <= W - 4) orow[x0 + p] = r[p];
        }
        return;
    }

    // -------------------- Boundary path --------------------
    int idx = blk * 128 + threadIdx.x;           // 0 .. 30719
    if (idx >= 3 * 10215) return;
    int c = idx / 10215;
    int b = idx - c * 10215;

    int y, x;
    if (b < 2048) {                     // rows 0..1
        y = b >> 10; x = b & 1023;
    } else if (b < 5120) {              // rows 1021..1023
        int r = b - 2048; y = 1021 + (r >> 10); x = r & 1023;
    } else {                            // rows 2..1020, cols {0,1,1021,1022,1023}
        int r = b - 5120;
        int q = r / 5;
        int s = r - q * 5;
        y = 2 + q;
        x = (s < 2) ? s : 1019 + s;
    }

    const float* cimg = img + ((size_t)c << 20);

    float v[25];
    int inv = 0;

#pragma unroll
    for (int ky = 0; ky < 5; ++ky) {
        int yy = y + ky - 2;
        bool vy = (yy >= 0) && (yy <= H - 2);
        int  yc = min(max(yy, 0), H - 1);
        const float* row = cimg + (size_t)yc * W;
#pragma unroll
        for (int kx = 0; kx < 5; ++kx) {
            int xx = x + kx - 2;
            bool vx = (xx >= 0) && (xx <= W - 2);
            int  xc = min(max(xx, 0), W - 1);
            float val = __ldg(row + xc);
            if (!(vy && vx)) {
                val = __int_as_float((inv & 1) ? 0x7f800000u : 0xff800000u);
                ++inv;
            }
            v[ky * 5 + kx] = val;
        }
    }

#pragma unroll
    for (int i = 0; i < BNET.n; ++i) {
        const int a = BNET.p[i].a, b2 = BNET.p[i].b;
        const int op = BNET.p[i].op;
        if (op == 0) {
            float mn = fminf(v[a], v[b2]);
            float mx = fmaxf(v[a], v[b2]);
            v[a] = mn;
            v[b2] = mx;
        } else if (op == 1) {
            v[a] = fminf(v[a], v[b2]);
        } else {
            v[b2] = fmaxf(v[a], v[b2]);
        }
    }

    float s12 = v[12];
    float s13 = v[13];
    float hi  = (inv & 1) ? s13 : s12;
    out[((size_t)c << 20) + (size_t)y * W + x] = 0.5f * (s12 + hi);
}

extern "C" void kernel_launch(void* const* d_in, const int* in_sizes, int n_in,
                              void* d_out, int out_size) {
    const float* img = (const float*)d_in[0];
    float* out = (float*)d_out;
    median_fused<<<NB_BOUND + NB_INNER, 128>>>(img, out);
}

// round 7
// speedup vs baseline: 3.2202x; 1.4721x over previous
#include <cuda_runtime.h>

// ============================================================================
// Compile-time network machinery.
//  - Batcher odd-even mergesort (power-of-2) + prefix restriction.
//  - Generalized odd-even merge on index lists (oem2), each stage verified
//    exhaustively at compile time via the 0-1 principle.
//  - Global program over 72 slots: column sorts, shared merges, COPY ops,
//    interval-pruned final merges; one global backward slice with op-level
//    pruning (min-only / max-only / both) and copy liveness.
//  - Interval pruning theorem: for rank-12 of union(A sorted 20, B sorted 5),
//    A[i] has union position in [i, i+5], so A[0..6] always rank below 12 and
//    A[13..19] always above; the answer is index 5 of sorted(A[7..12] u B).
// ============================================================================

struct P8 { unsigned char a, b; };
struct Op { unsigned char t, a, b, op; };  // t: 0=CE, 1=COPY(a <- b)
struct CE3 { unsigned char a, b, op; };    // op: 0=both, 1=min-only, 2=max-only

constexpr void oem_merge(int lo, int n, int r, P8* out, int& cnt) {
    int m = r * 2;
    if (m < n) {
        oem_merge(lo,     n, m, out, cnt);
        oem_merge(lo + r, n, m, out, cnt);
        for (int i = lo + r; i + r < lo + n; i += m)
            out[cnt++] = P8{(unsigned char)i, (unsigned char)(i + r)};
    } else {
        out[cnt++] = P8{(unsigned char)lo, (unsigned char)(lo + r)};
    }
}

constexpr void oem_sort(int lo, int n, P8* out, int& cnt) {
    if (n > 1) {
        int m = n / 2;
        oem_sort(lo,     m, out, cnt);
        oem_sort(lo + m, m, out, cnt);
        oem_merge(lo, n, 1, out, cnt);
    }
}

// ---- sort-5 network: Batcher sort-8 restricted to slots < 5 (9 CEs).
struct Net5 { int n; P8 p[24]; };

constexpr Net5 build_sort5() {
    P8 all[64] = {};
    int cnt = 0;
    oem_sort(0, 8, all, cnt);
    Net5 s = {};
    for (int i = 0; i < cnt; ++i)
        if (all[i].a < 5 && all[i].b < 5)
            s.p[s.n++] = all[i];
    return s;
}

constexpr bool verify_sort5(const Net5& s) {
    for (int m = 0; m < 32; ++m) {
        int v[5] = {};
        for (int k = 0; k < 5; ++k) v[k] = (m >> k) & 1;
        for (int i = 0; i < s.n; ++i) {
            int a = s.p[i].a, b = s.p[i].b;
            if (v[a] > v[b]) { int t = v[a]; v[a] = v[b]; v[b] = t; }
        }
        for (int k = 0; k + 1 < 5; ++k)
            if (v[k] > v[k + 1]) return false;
    }
    return true;
}

static_assert(verify_sort5(build_sort5()), "sort5 network invalid");

// ---- Generalized odd-even merge on index lists (Knuth 5.2.2-style).
constexpr void oem2(const int* A, int m, const int* B, int n, int* Z,
                    P8* ce, int& cnt) {
    if (m == 0) { for (int i = 0; i < n; ++i) Z[i] = B[i]; return; }
    if (n == 0) { for (int i = 0; i < m; ++i) Z[i] = A[i]; return; }
    if (m == 1 && n == 1) {
        ce[cnt++] = P8{(unsigned char)A[0], (unsigned char)B[0]};
        Z[0] = A[0]; Z[1] = B[0];
        return;
    }
    int Ae[25] = {}, Ao[25] = {}, Be[25] = {}, Bo[25] = {};
    int nae = 0, nao = 0, nbe = 0, nbo = 0;
    for (int i = 0; i < m; ++i) { if (i & 1) Ao[nao++] = A[i]; else Ae[nae++] = A[i]; }
    for (int i = 0; i < n; ++i) { if (i & 1) Bo[nbo++] = B[i]; else Be[nbe++] = B[i]; }
    int E[25] = {}, O[25] = {};
    oem2(Ae, nae, Be, nbe, E, ce, cnt);
    oem2(Ao, nao, Bo, nbo, O, ce, cnt);
    int ne = nae + nbe, no = nao + nbo;
    Z[0] = E[0];
    int zi = 1;
    int i = 0;
    for (; i < no && i + 1 < ne; ++i) {
        ce[cnt++] = P8{(unsigned char)O[i], (unsigned char)E[i + 1]};
        Z[zi++] = O[i];
        Z[zi++] = E[i + 1];
    }
    for (; i < no; ++i) Z[zi++] = O[i];
    for (int j = i + 1; j < ne; ++j) Z[zi++] = E[j];
}

// Exhaustive 0-1 verification of one merge stage over an 80-slot space.
constexpr bool verify_merge80(const P8* ce, int ibeg, int iend,
                              const int* A, int m, const int* B, int n,
                              const int* Z) {
    for (int i = 0; i <= m; ++i) {
        for (int j = 0; j <= n; ++j) {
            int v[80] = {};
            for (int k = 0; k < m; ++k) v[A[k]] = (k >= m - i) ? 1 : 0;
            for (int k = 0; k < n; ++k) v[B[k]] = (k >= n - j) ? 1 : 0;
            for (int t = ibeg; t < iend; ++t) {
                int a = ce[t].a, b = ce[t].b;
                if (v[a] > v[b]) { int tmp = v[a]; v[a] = v[b]; v[b] = tmp; }
            }
            for (int k = 0; k + 1 < m + n; ++k)
                if (v[Z[k]] > v[Z[k + 1]]) return false;
        }
    }
    return true;
}

// ---- Boundary network: sort-25 sliced for {12,13} with op-level pruning.
struct Net { int n; CE3 p[256]; };

constexpr Net slice_net25(const P8* ce, int cnt, const bool* outputs_needed) {
    bool need[25] = {};
    for (int i = 0; i < 25; ++i) need[i] = outputs_needed[i];
    signed char op[256] = {};
    bool keep[256] = {};
    for (int i = cnt - 1; i >= 0; --i) {
        bool na = need[ce[i].a], nb = need[ce[i].b];
        if (!na && !nb) continue;
        keep[i] = true;
        op[i] = (na && nb) ? 0 : (na ? 1 : 2);
        need[ce[i].a] = true;
        need[ce[i].b] = true;
    }
    Net net = {};
    for (int i = 0; i < cnt; ++i)
        if (keep[i])
            net.p[net.n++] = CE3{ce[i].a, ce[i].b, (unsigned char)op[i]};
    return net;
}

constexpr Net build_boundary_net() {
    P8 all[256] = {};
    int cnt = 0;
    oem_sort(0, 32, all, cnt);
    P8 filt[256] = {};
    int fc = 0;
    for (int i = 0; i < cnt; ++i)
        if (all[i].a < 25 && all[i].b < 25)
            filt[fc++] = all[i];
    bool outs[25] = {};
    outs[12] = true;
    outs[13] = true;
    return slice_net25(filt, fc, outs);
}

__device__ constexpr Net BNET = build_boundary_net();

// ---- Global interior program over 72 slots.
// Slots 0..39: sorted columns c0..c7 (col j at 5j..5j+4).
// 40..44: copy of sorted c2 (T2), 45..49: copy of sorted c5 (T5),
// 50..59: copy of m34 (T34), 60..65: U (copy of m1234[7..12]),
// 66..71: V (copy of m3456[7..12]).
struct Prog { int n; Op p[420]; unsigned char outslot[4]; bool ok; };

constexpr Prog build_prog() {
    Op ops[512] = {};
    int oc = 0;
    bool ok = true;

    // Column sorts.
    {
        Net5 s5 = build_sort5();
        for (int j = 0; j < 8; ++j)
            for (int i = 0; i < s5.n; ++i)
                ops[oc++] = Op{0, (unsigned char)(5 * j + s5.p[i].a),
                                  (unsigned char)(5 * j + s5.p[i].b), 0};
    }

    int C[8][5] = {};
    for (int j = 0; j < 8; ++j)
        for (int k = 0; k < 5; ++k) C[j][k] = 5 * j + k;

    // Copies of sorted c2, c5 (their originals get consumed by m12/m56).
    int T2[5] = {}, T5[5] = {};
    for (int k = 0; k < 5; ++k) { T2[k] = 40 + k; ops[oc++] = Op{1, (unsigned char)(40 + k), (unsigned char)C[2][k], 0}; }
    for (int k = 0; k < 5; ++k) { T5[k] = 45 + k; ops[oc++] = Op{1, (unsigned char)(45 + k), (unsigned char)C[5][k], 0}; }

    int Z12[10] = {}, Z34[10] = {}, Z56[10] = {}, Z1234[20] = {}, Z3456[20] = {};

    // m12 = merge(c1, c2)
    {
        P8 t[160] = {}; int tc = 0;
        oem2(C[1], 5, C[2], 5, Z12, t, tc);
        ok = ok && verify_merge80(t, 0, tc, C[1], 5, C[2], 5, Z12);
        for (int i = 0; i < tc; ++i) ops[oc++] = Op{0, t[i].a, t[i].b, 0};
    }
    // m34 = merge(c3, c4)
    {
        P8 t[160] = {}; int tc = 0;
        oem2(C[3], 5, C[4], 5, Z34, t, tc);
        ok = ok && verify_merge80(t, 0, tc, C[3], 5, C[4], 5, Z34);
        for (int i = 0; i < tc; ++i) ops[oc++] = Op{0, t[i].a, t[i].b, 0};
    }
    // m56 = merge(c5, c6)
    {
        P8 t[160] = {}; int tc = 0;
        oem2(C[5], 5, C[6], 5, Z56, t, tc);
        ok = ok && verify_merge80(t, 0, tc, C[5], 5, C[6], 5, Z56);
        for (int i = 0; i < tc; ++i) ops[oc++] = Op{0, t[i].a, t[i].b, 0};
    }

    // Copy m34 -> T34 (m1234 consumes Z34 in place; m3456 uses the copy).
    int T34[10] = {};
    for (int k = 0; k < 10; ++k) { T34[k] = 50 + k; ops[oc++] = Op{1, (unsigned char)(50 + k), (unsigned char)Z34[k], 0}; }

    // m1234 = merge(m12, m34)
    {
        P8 t[160] = {}; int tc = 0;
        oem2(Z12, 10, Z34, 10, Z1234, t, tc);
        ok = ok && verify_merge80(t, 0, tc, Z12, 10, Z34, 10, Z1234);
        for (int i = 0; i < tc; ++i) ops[oc++] = Op{0, t[i].a, t[i].b, 0};
    }
    // m3456 = merge(T34, m56)
    {
        P8 t[160] = {}; int tc = 0;
        oem2(T34, 10, Z56, 10, Z3456, t, tc);
        ok = ok && verify_merge80(t, 0, tc, T34, 10, Z56, 10, Z3456);
        for (int i = 0; i < tc; ++i) ops[oc++] = Op{0, t[i].a, t[i].b, 0};
    }

    // Candidate windows (interval pruning): only A[7..12] of each 20-merge can
    // hold the global rank-12 element; rank within candidates = 5.
    int A01[6] = {}, A23[6] = {};
    for (int k = 0; k < 6; ++k) { A01[k] = Z1234[7 + k]; A23[k] = Z3456[7 + k]; }

    int U[6] = {}, V[6] = {};
    for (int k = 0; k < 6; ++k) { U[k] = 60 + k; ops[oc++] = Op{1, (unsigned char)(60 + k), (unsigned char)A01[k], 0}; }
    for (int k = 0; k < 6; ++k) { V[k] = 66 + k; ops[oc++] = Op{1, (unsigned char)(66 + k), (unsigned char)A23[k], 0}; }

    unsigned char outs[4] = {};

    // px0: merge(U, c0), out = idx 5.
    {
        int ZF[11] = {}; P8 t[160] = {}; int tc = 0;
        oem2(U, 6, C[0], 5, ZF, t, tc);
        ok = ok && verify_merge80(t, 0, tc, U, 6, C[0], 5, ZF);
        for (int i = 0; i < tc; ++i) ops[oc++] = Op{0, t[i].a, t[i].b, 0};
        outs[0] = (unsigned char)ZF[5];
    }
    // px1: merge(A01 in place, T5), out = idx 5.
    {
        int ZF[11] = {}; P8 t[160] = {}; int tc = 0;
        oem2(A01, 6, T5, 5, ZF, t, tc);
        ok = ok && verify_merge80(t, 0, tc, A01, 6, T5, 5, ZF);
        for (int i = 0; i < tc; ++i) ops[oc++] = Op{0, t[i].a, t[i].b, 0};
        outs[1] = (unsigned char)ZF[5];
    }
    // px2: merge(V, T2), out = idx 5.
    {
        int ZF[11] = {}; P8 t[160] = {}; int tc = 0;
        oem2(V, 6, T2, 5, ZF, t, tc);
        ok = ok && verify_merge80(t, 0, tc, V, 6, T2, 5, ZF);
        for (int i = 0; i < tc; ++i) ops[oc++] = Op{0, t[i].a, t[i].b, 0};
        outs[2] = (unsigned char)ZF[5];
    }
    // px3: merge(A23 in place, c7), out = idx 5.
    {
        int ZF[11] = {}; P8 t[160] = {}; int tc = 0;
        oem2(A23, 6, C[7], 5, ZF, t, tc);
        ok = ok && verify_merge80(t, 0, tc, A23, 6, C[7], 5, ZF);
        for (int i = 0; i < tc; ++i) ops[oc++] = Op{0, t[i].a, t[i].b, 0};
        outs[3] = (unsigned char)ZF[5];
    }

    // Global backward slice with op-level pruning + copy liveness.
    bool need[80] = {};
    for (int i = 0; i < 4; ++i) need[outs[i]] = true;
    bool keep[512] = {};
    unsigned char opc[512] = {};
    for (int i = oc - 1; i >= 0; --i) {
        if (ops[i].t == 1) {                 // COPY a <- b
            if (need[ops[i].a]) {
                keep[i] = true;
                need[ops[i].b] = true;
                need[ops[i].a] = false;      // a redefined here
            }
        } else {                             // CE
            bool na = need[ops[i].a], nb = need[ops[i].b];
            if (na || nb) {
                keep[i] = true;
                opc[i] = (na && nb) ? 0 : (na ? 1 : 2);
                need[ops[i].a] = true;
                need[ops[i].b] = true;
            }
        }
    }

    Prog pr = {};
    pr.ok = ok;
    for (int i = 0; i < oc; ++i)
        if (keep[i]) {
            pr.p[pr.n] = ops[i];
            pr.p[pr.n].op = opc[i];
            ++pr.n;
        }
    for (int i = 0; i < 4; ++i) pr.outslot[i] = outs[i];
    return pr;
}

__device__ constexpr Prog PROG = build_prog();
static_assert(build_prog().ok, "interior merge verification failed");
static_assert(build_prog().n <= 420, "program overflow");

// ============================================================================
// Fused kernel
// ============================================================================

#define MF_C 3
#define MF_H 1024
#define MF_W 1024

#define NB_BOUND 240
#define NB_INNER 6114

__global__ __launch_bounds__(128)
void median_fused(const float* __restrict__ img, float* __restrict__ out) {
    constexpr int H = MF_H, W = MF_W;
    int blk = blockIdx.x;

    if (blk >= NB_BOUND) {
        // -------------------- Interior path --------------------
        int ib = blk - NB_BOUND;                 // 0 .. 6113
        int bx = ib & 1;
        int rem = ib >> 1;
        int yrow = rem % 1019;
        int c = rem / 1019;
        int t = bx * 128 + threadIdx.x;
        if (t >= 255) return;
        int y = yrow + 2;

        const float* base = img + ((size_t)c << 20) + (size_t)(y - 2) * W + 4 * t;

        float w[72];
#pragma unroll
        for (int k = 0; k < 5; ++k) {
            float4 a = *reinterpret_cast<const float4*>(base + (size_t)k * W);
            float4 b = *reinterpret_cast<const float4*>(base + (size_t)k * W + 4);
            w[0 + k]  = a.x; w[5 + k]  = a.y; w[10 + k] = a.z; w[15 + k] = a.w;
            w[20 + k] = b.x; w[25 + k] = b.y; w[30 + k] = b.z; w[35 + k] = b.w;
        }

        // Unified sliced program: sorts, copies, shared merges, finals.
#pragma unroll
        for (int i = 0; i < PROG.n; ++i) {
            const int tt = PROG.p[i].t;
            const int a = PROG.p[i].a, b = PROG.p[i].b;
            const int op = PROG.p[i].op;
            if (tt == 1) {
                w[a] = w[b];
            } else if (op == 0) {
                float mn = fminf(w[a], w[b]);
                float mx = fmaxf(w[a], w[b]);
                w[a] = mn;
                w[b] = mx;
            } else if (op == 1) {
                w[a] = fminf(w[a], w[b]);
            } else {
                w[b] = fmaxf(w[a], w[b]);
            }
        }

        int x0 = 2 + 4 * t;
        float* orow = out + ((size_t)c << 20) + (size_t)y * W;
        bool full = (t < 254);

        float r[4];
#pragma unroll
        for (int p = 0; p < 4; ++p) r[p] = w[PROG.outslot[p]];

        if (full) {
#pragma unroll
            for (int p = 0; p < 4; ++p) orow[x0 + p] = r[p];
        } else {
#pragma unroll
            for (int p = 0; p < 4; ++p)
                if (x0 + p <= W - 4) orow[x0 + p] = r[p];
        }
        return;
    }

    // -------------------- Boundary path --------------------
    int idx = blk * 128 + threadIdx.x;           // 0 .. 30719
    if (idx >= 3 * 10215) return;
    int c = idx / 10215;
    int b = idx - c * 10215;

    int y, x;
    if (b < 2048) {                     // rows 0..1
        y = b >> 10; x = b & 1023;
    } else if (b < 5120) {              // rows 1021..1023
        int r = b - 2048; y = 1021 + (r >> 10); x = r & 1023;
    } else {                            // rows 2..1020, cols {0,1,1021,1022,1023}
        int r = b - 5120;
        int q = r / 5;
        int s = r - q * 5;
        y = 2 + q;
        x = (s < 2) ? s : 1019 + s;
    }

    const float* cimg = img + ((size_t)c << 20);

    float v[25];
    int inv = 0;

#pragma unroll
    for (int ky = 0; ky < 5; ++ky) {
        int yy = y + ky - 2;
        bool vy = (yy >= 0) && (yy <= H - 2);
        int  yc = min(max(yy, 0), H - 1);
        const float* row = cimg + (size_t)yc * W;
#pragma unroll
        for (int kx = 0; kx < 5; ++kx) {
            int xx = x + kx - 2;
            bool vx = (xx >= 0) && (xx <= W - 2);
            int  xc = min(max(xx, 0), W - 1);
            float val = __ldg(row + xc);
            if (!(vy && vx)) {
                val = __int_as_float((inv & 1) ? 0x7f800000u : 0xff800000u);
                ++inv;
            }
            v[ky * 5 + kx] = val;
        }
    }

#pragma unroll
    for (int i = 0; i < BNET.n; ++i) {
        const int a = BNET.p[i].a, b2 = BNET.p[i].b;
        const int op = BNET.p[i].op;
        if (op == 0) {
            float mn = fminf(v[a], v[b2]);
            float mx = fmaxf(v[a], v[b2]);
            v[a] = mn;
            v[b2] = mx;
        } else if (op == 1) {
            v[a] = fminf(v[a], v[b2]);
        } else {
            v[b2] = fmaxf(v[a], v[b2]);
        }
    }

    float s12 = v[12];
    float s13 = v[13];
    float hi  = (inv & 1) ? s13 : s12;
    out[((size_t)c << 20) + (size_t)y * W + x] = 0.5f * (s12 + hi);
}

extern "C" void kernel_launch(void* const* d_in, const int* in_sizes, int n_in,
                              void* d_out, int out_size) {
    const float* img = (const float*)d_in[0];
    float* out = (float*)d_out;
    median_fused<<<NB_BOUND + NB_INNER, 128>>>(img, out);
}